// round 14
// baseline (speedup 1.0000x reference)
#include <cuda_runtime.h>
#include <cuda_bf16.h>
#include <cstdint>
#include <cstddef>

#define D     512
#define DDm   (D * D)
#define Tt    4096
#define BSZ   8
#define NSLOT 16      // 0..7: A^1..A^8 ; 8..14: A^16,A^24..A^64 ; 15: B
#define KC    32
#define NCHK  16
#define STRB  40      // smem row stride in bf16 (80 B) -> conflict-free ldmatrix

__device__ __nv_bfloat16 g_PH[NSLOT * DDm];   // powers hi, row-major (A operand)
__device__ __nv_bfloat16 g_PL[NSLOT * DDm];   // lo
__device__ __nv_bfloat16 g_PTH[NSLOT * DDm];  // transposed hi (B operand for POW)
__device__ __nv_bfloat16 g_PTL[NSLOT * DDm];
__device__ float g_Pf[DDm];                   // fp32 A^64 (for l34 scan)
__device__ float g_CB[(BSZ * 512) * D];
__device__ float g_DB[(BSZ * 64) * D];

enum { M_BX = 0, M_POW = 1, M_SCAN = 2, M_FIXZ = 3 };

__device__ __forceinline__ int i4sel(int4 v, int z) {
    return (z == 0) ? v.x : (z == 1) ? v.y : (z == 2) ? v.z : v.w;
}
__device__ __forceinline__ uint32_t s2u(const void* p) {
    uint32_t a;
    asm("{ .reg .u64 t; cvta.to.shared.u64 t, %1; cvt.u32.u64 %0, t; }" : "=r"(a) : "l"(p));
    return a;
}
__device__ __forceinline__ void split8(float4 a, float4 b, uint4& H, uint4& L) {
    __nv_bfloat162 h0 = __float22bfloat162_rn(make_float2(a.x, a.y));
    __nv_bfloat162 h1 = __float22bfloat162_rn(make_float2(a.z, a.w));
    __nv_bfloat162 h2 = __float22bfloat162_rn(make_float2(b.x, b.y));
    __nv_bfloat162 h3 = __float22bfloat162_rn(make_float2(b.z, b.w));
    float2 f0 = __bfloat1622float2(h0), f1 = __bfloat1622float2(h1);
    float2 f2 = __bfloat1622float2(h2), f3 = __bfloat1622float2(h3);
    __nv_bfloat162 l0 = __float22bfloat162_rn(make_float2(a.x - f0.x, a.y - f0.y));
    __nv_bfloat162 l1 = __float22bfloat162_rn(make_float2(a.z - f1.x, a.w - f1.y));
    __nv_bfloat162 l2 = __float22bfloat162_rn(make_float2(b.x - f2.x, b.y - f2.y));
    __nv_bfloat162 l3 = __float22bfloat162_rn(make_float2(b.z - f3.x, b.w - f3.y));
    H.x = *(uint32_t*)&h0; H.y = *(uint32_t*)&h1; H.z = *(uint32_t*)&h2; H.w = *(uint32_t*)&h3;
    L.x = *(uint32_t*)&l0; L.y = *(uint32_t*)&l1; L.z = *(uint32_t*)&l2; L.w = *(uint32_t*)&l3;
}
__device__ __forceinline__ void ldm4(uint32_t* r, uint32_t addr) {
    asm volatile("ldmatrix.sync.aligned.m8n8.x4.shared.b16 {%0,%1,%2,%3}, [%4];"
                 : "=r"(r[0]), "=r"(r[1]), "=r"(r[2]), "=r"(r[3]) : "r"(addr));
}
__device__ __forceinline__ void mma16816(float* c, const uint32_t* a, const uint32_t* b) {
    asm volatile("mma.sync.aligned.m16n8k16.row.col.f32.bf16.bf16.f32 "
                 "{%0,%1,%2,%3}, {%4,%5,%6,%7}, {%8,%9}, {%0,%1,%2,%3};"
                 : "+f"(c[0]), "+f"(c[1]), "+f"(c[2]), "+f"(c[3])
                 : "r"(a[0]), "r"(a[1]), "r"(a[2]), "r"(a[3]), "r"(b[0]), "r"(b[1]));
}
__device__ __forceinline__ void cpa16(uint32_t d, const void* s) {
    asm volatile("cp.async.cg.shared.global [%0], [%1], 16;" :: "r"(d), "l"(s) : "memory");
}

// ---------------------------------------------------------------------------
// HMMA unified step: 128 e-rows (blockIdx.y) x CPB cols (blockIdx.x), K = 512.
// cp.async for bf16 operands; register-split path for fp32 X operands.
// ---------------------------------------------------------------------------
template <int CPB>
__global__ void __launch_bounds__(256, 2) tstep(
    const float* __restrict__ Xf, float* __restrict__ Of, float* __restrict__ Pf,
    int mode, int i, int Tl, int Cl, int shN, int aslot, int ncols,
    int4 za, int4 zx, int4 zd)
{
    constexpr int WN = CPB / 32;          // warps along N
    constexpr int MT = (128 * WN) / 128;  // m-tiles/warp: CPB=128 -> 4, CPB=64 -> 2
    constexpr int AHOF = 0, ALOF = 10240, XHOF = 20480;
    constexpr int XLOF = 20480 + CPB * 80;
    constexpr int STG  = 20480 + 2 * CPB * 80;
    constexpr int TPC = 256 / CPB;        // threads per X col: 2 (CPB=128) / 4 (CPB=64)
    constexpr int KPT = KC / TPC;         // k per X thread: 16 / 8
    constexpr int XF  = KPT / 4;          // float4 staged per X thread: 4 / 2
    static_assert(KPT >= 8 && XF >= 2, "X loader coverage");

    extern __shared__ char smem[];
    const uint32_t sbu = s2u(smem);
    const int tid = threadIdx.x, wid = tid >> 5, l = tid & 31;
    const int e0 = blockIdx.y * 128, c0 = blockIdx.x * CPB, z = blockIdx.z;
    const int mask = (1 << shN) - 1;
    const int wm = wid / WN, wn = wid % WN;

    const int as = (mode == M_POW) ? i4sel(za, z) : (mode == M_FIXZ) ? (aslot + z) : aslot;

    // ---- A loader (always bf16 tables, cp.async) ----
    const int aRow = tid >> 1, aKq = (tid & 1) * 16;
    const __nv_bfloat16* pAH = g_PH + (size_t)as * DDm + (size_t)(e0 + aRow) * D + aKq;
    const __nv_bfloat16* pAL = g_PL + (size_t)as * DDm + (size_t)(e0 + aRow) * D + aKq;
    const uint32_t sAo = (uint32_t)(aRow * STRB + aKq) * 2;

    // ---- X loader: CPB cols x KC k over 256 threads ----
    const int xc = tid / TPC, xkq = (tid % TPC) * KPT;
    const uint32_t sXo = (uint32_t)(xc * STRB + xkq) * 2;
    const float* xfp = nullptr;
    const __nv_bfloat16 *pXH = nullptr, *pXL = nullptr;
    if (mode == M_POW) {
        const int xs = i4sel(zx, z);
        pXH = g_PTH + (size_t)xs * DDm + (size_t)(c0 + xc) * D + xkq;
        pXL = g_PTL + (size_t)xs * DDm + (size_t)(c0 + xc) * D + xkq;
    } else {
        const int c = c0 + xc;
        if (mode == M_SCAN) {
            const int b = c >> shN, j = c & mask;
            xfp = Of + ((size_t)b * Tl + (size_t)j * Cl + (i - 1)) * D + xkq;
        } else {
            xfp = Xf + (size_t)c * D + xkq;
        }
    }

    float acc[MT][4][4];
#pragma unroll
    for (int a = 0; a < MT; a++)
#pragma unroll
        for (int b = 0; b < 4; b++)
#pragma unroll
            for (int q = 0; q < 4; q++) acc[a][b][q] = 0.f;

    float4 f[XF];

#define ASYNC_AB(CH, S) do { const int _k = (CH) * KC;                        \
        uint32_t _d = sbu + (S) * STG + AHOF + sAo;                           \
        cpa16(_d, pAH + _k); cpa16(_d + 16, pAH + _k + 8);                    \
        cpa16(_d + (ALOF - AHOF), pAL + _k);                                  \
        cpa16(_d + (ALOF - AHOF) + 16, pAL + _k + 8);                         \
        if (mode == M_POW) {                                                  \
            uint32_t _x = sbu + (S) * STG + XHOF + sXo;                       \
            _Pragma("unroll") for (int u = 0; u < KPT / 8; u++) {             \
                cpa16(_x + u * 16, pXH + _k + u * 8);                         \
                cpa16(_x + (XLOF - XHOF) + u * 16, pXL + _k + u * 8);         \
            }                                                                 \
        }                                                                     \
        asm volatile("cp.async.commit_group;" ::: "memory");                  \
    } while (0)

#define FETCHX(CH) do { const int _k = (CH) * KC;                             \
        _Pragma("unroll") for (int u = 0; u < XF; u++)                        \
            f[u] = *(const float4*)(xfp + _k + u * 4);                        \
    } while (0)

#define STOREX(S) do { char* _b = smem + (S) * STG;                           \
        _Pragma("unroll") for (int u = 0; u < XF / 2; u++) {                  \
            uint4 _H, _L; split8(f[2 * u], f[2 * u + 1], _H, _L);             \
            *(uint4*)(_b + XHOF + sXo + u * 16) = _H;                         \
            *(uint4*)(_b + XLOF + sXo + u * 16) = _L;                         \
        }                                                                     \
    } while (0)

#define COMPUTE(S) do { const uint32_t stb = sbu + (S) * STG;                 \
        _Pragma("unroll")                                                     \
        for (int ks = 0; ks < 2; ks++) {                                      \
            const int k0 = ks * 16;                                           \
            uint32_t bh[4][2], bl[4][2];                                      \
            _Pragma("unroll")                                                 \
            for (int p = 0; p < 2; p++) {                                     \
                const uint32_t nrow = wn * 32 + p * 16 + (l & 7) + ((l >> 4) << 3); \
                const uint32_t koff = k0 + (((l >> 3) & 1) << 3);             \
                const uint32_t ax = stb + XHOF + (nrow * STRB + koff) * 2;    \
                uint32_t r[4];                                                \
                ldm4(r, ax);                                                  \
                bh[2*p][0] = r[0]; bh[2*p][1] = r[1];                         \
                bh[2*p+1][0] = r[2]; bh[2*p+1][1] = r[3];                     \
                ldm4(r, ax + (XLOF - XHOF));                                  \
                bl[2*p][0] = r[0]; bl[2*p][1] = r[1];                         \
                bl[2*p+1][0] = r[2]; bl[2*p+1][1] = r[3];                     \
            }                                                                 \
            _Pragma("unroll")                                                 \
            for (int mt = 0; mt < MT; mt++) {                                 \
                const uint32_t mrow = wm * (MT * 16) + mt * 16 + (l & 15);    \
                const uint32_t koffA = k0 + ((l >> 4) << 3);                  \
                const uint32_t aa = stb + AHOF + (mrow * STRB + koffA) * 2;   \
                uint32_t ah[4], al[4];                                        \
                ldm4(ah, aa); ldm4(al, aa + (ALOF - AHOF));                   \
                _Pragma("unroll")                                             \
                for (int nt = 0; nt < 4; nt++) {                              \
                    mma16816(acc[mt][nt], ah, bh[nt]);                        \
                    mma16816(acc[mt][nt], ah, bl[nt]);                        \
                    mma16816(acc[mt][nt], al, bh[nt]);                        \
                }                                                             \
            }                                                                 \
        }                                                                     \
    } while (0)

    ASYNC_AB(0, 0);
    if (mode != M_POW) FETCHX(0);
    asm volatile("cp.async.wait_group 0;" ::: "memory");
    if (mode != M_POW) STOREX(0);
    __syncthreads();

    for (int ch = 0; ch < NCHK; ch++) {
        const bool more = (ch + 1 < NCHK);
        if (more) {
            ASYNC_AB(ch + 1, (ch + 1) & 1);
            if (mode != M_POW) FETCHX(ch + 1);
        }
        COMPUTE(ch & 1);
        if (more) {
            asm volatile("cp.async.wait_group 0;" ::: "memory");
            if (mode != M_POW) STOREX((ch + 1) & 1);
            __syncthreads();
        }
    }

    // ---------------- epilogue ----------------
#pragma unroll
    for (int mt = 0; mt < MT; mt++)
#pragma unroll
    for (int nt = 0; nt < 4; nt++) {
        float* cc = acc[mt][nt];
        const int cpa = c0 + wn * 32 + nt * 8 + (l & 3) * 2;
        const int elo = e0 + wm * (MT * 16) + mt * 16 + (l >> 2);
        if (cpa >= ncols) continue;
        if (mode == M_BX) {
            Of[(size_t)cpa * D + elo] = cc[0];
            Of[(size_t)(cpa + 1) * D + elo] = cc[1];
            Of[(size_t)cpa * D + elo + 8] = cc[2];
            Of[(size_t)(cpa + 1) * D + elo + 8] = cc[3];
        } else if (mode == M_POW) {
            const int zds = i4sel(zd, z);
#pragma unroll
            for (int q = 0; q < 4; q++) {
                const int e = elo + ((q >> 1) << 3);
                const int c = cpa + (q & 1);
                const float v = cc[q];
                __nv_bfloat16 h = __float2bfloat16(v);
                __nv_bfloat16 lo = __float2bfloat16(v - __bfloat162float(h));
                const size_t rm = (size_t)zds * DDm + (size_t)e * D + c;
                const size_t tm = (size_t)zds * DDm + (size_t)c * D + e;
                g_PH[rm] = h; g_PL[rm] = lo;
                g_PTH[tm] = h; g_PTL[tm] = lo;
                if (zds == 14) g_Pf[(size_t)e * D + c] = v;   // fp32 A^64
            }
        } else if (mode == M_SCAN) {
            const int b = cpa >> shN, j = cpa & mask;
            float* p0 = Of + ((size_t)b * Tl + (size_t)j * Cl + i) * D;
            float* p1 = p0 + (size_t)Cl * D;
            const float s0 = p0[elo] + cc[0];      p0[elo] = s0;
            const float s1 = p1[elo] + cc[1];      p1[elo] = s1;
            const float s2 = p0[elo + 8] + cc[2];  p0[elo + 8] = s2;
            const float s3 = p1[elo + 8] + cc[3];  p1[elo + 8] = s3;
            if (i == Cl - 1) {
                float* fw = Pf + ((size_t)b * (mask + 1) + j + 1) * D;
                fw[elo] = s0; fw[elo + 8] = s2;    // j even -> j < mask
                if (j + 1 < mask) {
                    float* f2 = Pf + ((size_t)b * (mask + 1) + j + 2) * D;
                    f2[elo] = s1; f2[elo + 8] = s3;
                }
            }
        } else {  // M_FIXZ
            const int b = cpa >> shN, j = cpa & mask;
            float* p0 = Of + ((size_t)b * Tl + (size_t)j * Cl + z) * D;
            float* p1 = p0 + (size_t)Cl * D;
            p0[elo] += cc[0]; p1[elo] += cc[1];
            p0[elo + 8] += cc[2]; p1[elo + 8] += cc[3];
        }
    }
#undef ASYNC_AB
#undef FETCHX
#undef STOREX
#undef COMPUTE
}

// ---------------- prep: split A (slot 0) and B (slot 15) ----------------
__global__ void prep_split(const float* __restrict__ A, const float* __restrict__ Bm) {
    const int idx = blockIdx.x * blockDim.x + threadIdx.x;  // 2*DDm
    const int off = idx & (DDm - 1);
    const int slot = (idx < DDm) ? 0 : 15;
    const float v = ((idx < DDm) ? A : Bm)[off];
    const int e = off >> 9, d = off & 511;
    __nv_bfloat16 h = __float2bfloat16(v);
    __nv_bfloat16 lo = __float2bfloat16(v - __bfloat162float(h));
    const size_t rm = (size_t)slot * DDm + off;
    const size_t tm = (size_t)slot * DDm + (size_t)d * D + e;
    g_PH[rm] = h; g_PL[rm] = lo;
    g_PTH[tm] = h; g_PTL[tm] = lo;
}

__global__ void seed_levels(const float* __restrict__ h0) {
    const int b = blockIdx.x, t = threadIdx.x;
    g_CB[(size_t)b * 512 * D + t] = h0[(size_t)b * D + t];
    g_DB[(size_t)b * 64 * D + t] = 0.f;
}

// ---- per-batch sequential scan of the 64 level-3 states with fp32 A^64 ----
__global__ void __launch_bounds__(512) l34_scan() {
    __shared__ float s[D];
    const int b = blockIdx.x, t = threadIdx.x;
    s[t] = 0.f;                       // DB[b,0] = 0 (seeded)
    __syncthreads();
    const float* row = g_Pf + (size_t)t * D;
    for (int m = 1; m < 64; m++) {
        float acc = 0.f;
#pragma unroll 8
        for (int k = 0; k < D; k += 4) {
            float4 a = *(const float4*)(row + k);
            acc += a.x * s[k] + a.y * s[k + 1] + a.z * s[k + 2] + a.w * s[k + 3];
        }
        acc += g_DB[((size_t)b * 64 + m) * D + t];
        __syncthreads();
        s[t] = acc;
        g_DB[((size_t)b * 64 + m) * D + t] = acc;
        __syncthreads();
    }
}

// ---------------- launcher ----------------
extern "C" void kernel_launch(void* const* d_in, const int* in_sizes, int n_in,
                              void* d_out, int out_size) {
    (void)in_sizes; (void)n_in; (void)out_size;
    const float* x  = (const float*)d_in[0];
    const float* h0 = (const float*)d_in[1];
    const float* A  = (const float*)d_in[2];
    const float* Bm = (const float*)d_in[3];
    float* out = (float*)d_out;

    static float *pCB = nullptr, *pDB;
    if (!pCB) {
        cudaGetSymbolAddress((void**)&pCB, g_CB);
        cudaGetSymbolAddress((void**)&pDB, g_DB);
        cudaFuncSetAttribute(tstep<128>, cudaFuncAttributeMaxDynamicSharedMemorySize,
                             2 * (20480 + 2 * 128 * 80));
        cudaFuncSetAttribute(tstep<64>, cudaFuncAttributeMaxDynamicSharedMemorySize,
                             2 * (20480 + 2 * 64 * 80));
    }
    const int SM128 = 2 * (20480 + 2 * 128 * 80);
    const int SM64  = 2 * (20480 + 2 * 64 * 80);
    const int4 zz = make_int4(0, 0, 0, 0);
#define TSF(GX, GZ, ...) tstep<128><<<dim3(GX, 4, GZ), 256, SM128>>>(__VA_ARGS__)
#define TSS(GX, GZ, ...) tstep<64><<<dim3(GX, 4, GZ), 256, SM64>>>(__VA_ARGS__)

    prep_split<<<2 * DDm / 256, 256>>>(A, Bm);

    // Bx: out[:,m] = B * x[m,:]   (32768 cols)
    TSF(256, 1, x, out, nullptr, M_BX, 0, 0, 0, 0, 15, 32768, zz, zz, zz);

    // L1 local scan (A = slot 0), fold chunk ends -> CB[b, j+1]
    for (int i = 1; i < 8; i++)
        TSF(32, 1, nullptr, out, pCB, M_SCAN, i, Tt, 8, 9, 0, 4096, zz, zz, zz);

    seed_levels<<<BSZ, D>>>(h0);

    // power tables: A^2..A^8 (slots 1..7), A^16..A^64 (slots 8..14)
#define PW(ZC, AZ, XZ, DZ) \
    TSS(8, ZC, nullptr, nullptr, nullptr, M_POW, 0, 0, 0, 0, 0, 512, AZ, XZ, DZ)
    PW(1, make_int4(0,0,0,0),     make_int4(0,0,0,0),   make_int4(1,0,0,0));      // A^2
    PW(2, make_int4(1,1,0,0),     make_int4(0,1,0,0),   make_int4(2,3,0,0));      // A^3,A^4
    PW(4, make_int4(3,3,3,3),     make_int4(0,1,2,3),   make_int4(4,5,6,7));      // A^5..A^8
    PW(1, make_int4(7,0,0,0),     make_int4(7,0,0,0),   make_int4(8,0,0,0));      // A^16
    PW(2, make_int4(8,8,0,0),     make_int4(7,8,0,0),   make_int4(9,10,0,0));     // A^24,A^32
    PW(4, make_int4(10,10,10,10), make_int4(7,8,9,10),  make_int4(11,12,13,14));  // A^40..A^64
#undef PW

    // L2 local scan on CB (A^8 = slot 7), fold -> DB
    for (int i = 1; i < 8; i++)
        TSS(8, 1, nullptr, pCB, pDB, M_SCAN, i, 512, 8, 6, 7, 512, zz, zz, zz);

    // L3+L4: per-batch sequential scan of DB with fp32 A^64
    l34_scan<<<BSZ, D>>>();

    // L2 fixup: CB[:,8m+z] += A^{8(z+1)} * DB[:,m]
    TSS(8, 8, pDB, pCB, nullptr, M_FIXZ, 0, 512, 8, 6, 7, 512, zz, zz, zz);
    // L1 fixup: out[:,8j+z] += A^{z+1} * CB[:,j]
    TSF(32, 8, pCB, out, nullptr, M_FIXZ, 0, Tt, 8, 9, 0, 4096, zz, zz, zz);
#undef TSF
#undef TSS
}

// round 15
// speedup vs baseline: 1.0142x; 1.0142x over previous
#include <cuda_runtime.h>
#include <cuda_bf16.h>
#include <cstdint>
#include <cstddef>

#define D     512
#define DDm   (D * D)
#define Tt    4096
#define BSZ   8
#define NSLOT 16      // 0..7: A^1..A^8 ; 8..14: A^16,A^24..A^64 ; 15: B
#define KC    32
#define NCHK  16
#define STRB  40      // smem row stride in bf16 (80 B) -> conflict-free ldmatrix

__device__ __nv_bfloat16 g_PH[NSLOT * DDm];   // powers hi, row-major (A operand)
__device__ __nv_bfloat16 g_PL[NSLOT * DDm];   // lo
__device__ __nv_bfloat16 g_PTH[NSLOT * DDm];  // transposed hi (B operand for POW)
__device__ __nv_bfloat16 g_PTL[NSLOT * DDm];
__device__ float g_Pf[DDm];                   // fp32 A^64 (for l34 scan)
__device__ float g_CB[(BSZ * 512) * D];
__device__ float g_DB[(BSZ * 64) * D];

enum { M_BX = 0, M_POW = 1, M_SCAN = 2, M_FIXZ = 3 };

__device__ __forceinline__ int i4sel(int4 v, int z) {
    return (z == 0) ? v.x : (z == 1) ? v.y : (z == 2) ? v.z : v.w;
}
__device__ __forceinline__ uint32_t s2u(const void* p) {
    uint32_t a;
    asm("{ .reg .u64 t; cvta.to.shared.u64 t, %1; cvt.u32.u64 %0, t; }" : "=r"(a) : "l"(p));
    return a;
}
__device__ __forceinline__ void split8(float4 a, float4 b, uint4& H, uint4& L) {
    __nv_bfloat162 h0 = __float22bfloat162_rn(make_float2(a.x, a.y));
    __nv_bfloat162 h1 = __float22bfloat162_rn(make_float2(a.z, a.w));
    __nv_bfloat162 h2 = __float22bfloat162_rn(make_float2(b.x, b.y));
    __nv_bfloat162 h3 = __float22bfloat162_rn(make_float2(b.z, b.w));
    float2 f0 = __bfloat1622float2(h0), f1 = __bfloat1622float2(h1);
    float2 f2 = __bfloat1622float2(h2), f3 = __bfloat1622float2(h3);
    __nv_bfloat162 l0 = __float22bfloat162_rn(make_float2(a.x - f0.x, a.y - f0.y));
    __nv_bfloat162 l1 = __float22bfloat162_rn(make_float2(a.z - f1.x, a.w - f1.y));
    __nv_bfloat162 l2 = __float22bfloat162_rn(make_float2(b.x - f2.x, b.y - f2.y));
    __nv_bfloat162 l3 = __float22bfloat162_rn(make_float2(b.z - f3.x, b.w - f3.y));
    H.x = *(uint32_t*)&h0; H.y = *(uint32_t*)&h1; H.z = *(uint32_t*)&h2; H.w = *(uint32_t*)&h3;
    L.x = *(uint32_t*)&l0; L.y = *(uint32_t*)&l1; L.z = *(uint32_t*)&l2; L.w = *(uint32_t*)&l3;
}
__device__ __forceinline__ void ldm4(uint32_t* r, uint32_t addr) {
    asm volatile("ldmatrix.sync.aligned.m8n8.x4.shared.b16 {%0,%1,%2,%3}, [%4];"
                 : "=r"(r[0]), "=r"(r[1]), "=r"(r[2]), "=r"(r[3]) : "r"(addr));
}
__device__ __forceinline__ void mma16816(float* c, const uint32_t* a, const uint32_t* b) {
    asm volatile("mma.sync.aligned.m16n8k16.row.col.f32.bf16.bf16.f32 "
                 "{%0,%1,%2,%3}, {%4,%5,%6,%7}, {%8,%9}, {%0,%1,%2,%3};"
                 : "+f"(c[0]), "+f"(c[1]), "+f"(c[2]), "+f"(c[3])
                 : "r"(a[0]), "r"(a[1]), "r"(a[2]), "r"(a[3]), "r"(b[0]), "r"(b[1]));
}
__device__ __forceinline__ void cpa16(uint32_t d, const void* s) {
    asm volatile("cp.async.cg.shared.global [%0], [%1], 16;" :: "r"(d), "l"(s) : "memory");
}

// ---------------------------------------------------------------------------
// HMMA unified step: 128 e-rows (blockIdx.y) x 64 cols (blockIdx.x), K = 512.
// 8 warps (4m x 2n), warp tile 32x32 (MT=2).  cp.async for bf16 A (and X in
// POW mode); register-split path for fp32 X operands.
// ---------------------------------------------------------------------------
template <int CPB>
__global__ void __launch_bounds__(256, 2) tstep(
    const float* __restrict__ Xf, float* __restrict__ Of, float* __restrict__ Pf,
    int mode, int i, int Tl, int Cl, int shN, int aslot, int ncols,
    int4 za, int4 zx, int4 zd)
{
    constexpr int WN = CPB / 32;          // warps along N (2)
    constexpr int MT = (128 * WN) / 128;  // m-tiles/warp (2)
    constexpr int AHOF = 0, ALOF = 10240, XHOF = 20480;
    constexpr int XLOF = 20480 + CPB * 80;
    constexpr int STG  = 20480 + 2 * CPB * 80;
    constexpr int TPC = 256 / CPB;        // threads per X col (4)
    constexpr int KPT = KC / TPC;         // k per X thread (8)
    constexpr int XF  = KPT / 4;          // float4 staged per X thread (2)
    static_assert(KPT >= 8 && XF >= 2, "X loader coverage");

    extern __shared__ char smem[];
    const uint32_t sbu = s2u(smem);
    const int tid = threadIdx.x, wid = tid >> 5, l = tid & 31;
    const int e0 = blockIdx.y * 128, c0 = blockIdx.x * CPB, z = blockIdx.z;
    const int mask = (1 << shN) - 1;
    const int wm = wid / WN, wn = wid % WN;

    const int as = (mode == M_POW) ? i4sel(za, z) : (mode == M_FIXZ) ? (aslot + z) : aslot;

    // ---- A loader (bf16 tables, cp.async): 128 rows x 32 k ----
    const int aRow = tid >> 1, aKq = (tid & 1) * 16;
    const __nv_bfloat16* pAH = g_PH + (size_t)as * DDm + (size_t)(e0 + aRow) * D + aKq;
    const __nv_bfloat16* pAL = g_PL + (size_t)as * DDm + (size_t)(e0 + aRow) * D + aKq;
    const uint32_t sAo = (uint32_t)(aRow * STRB + aKq) * 2;

    // ---- X loader: CPB cols x KC k over 256 threads ----
    const int xc = tid / TPC, xkq = (tid % TPC) * KPT;
    const uint32_t sXo = (uint32_t)(xc * STRB + xkq) * 2;
    const float* xfp = nullptr;
    const __nv_bfloat16 *pXH = nullptr, *pXL = nullptr;
    if (mode == M_POW) {
        const int xs = i4sel(zx, z);
        pXH = g_PTH + (size_t)xs * DDm + (size_t)(c0 + xc) * D + xkq;
        pXL = g_PTL + (size_t)xs * DDm + (size_t)(c0 + xc) * D + xkq;
    } else {
        const int c = c0 + xc;
        if (mode == M_SCAN) {
            const int b = c >> shN, j = c & mask;
            xfp = Of + ((size_t)b * Tl + (size_t)j * Cl + (i - 1)) * D + xkq;
        } else {
            xfp = Xf + (size_t)c * D + xkq;
        }
    }

    float acc[MT][4][4];
#pragma unroll
    for (int a = 0; a < MT; a++)
#pragma unroll
        for (int b = 0; b < 4; b++)
#pragma unroll
            for (int q = 0; q < 4; q++) acc[a][b][q] = 0.f;

    float4 f[XF];

#define ASYNC_AB(CH, S) do { const int _k = (CH) * KC;                        \
        uint32_t _d = sbu + (S) * STG + AHOF + sAo;                           \
        cpa16(_d, pAH + _k); cpa16(_d + 16, pAH + _k + 8);                    \
        cpa16(_d + (ALOF - AHOF), pAL + _k);                                  \
        cpa16(_d + (ALOF - AHOF) + 16, pAL + _k + 8);                         \
        if (mode == M_POW) {                                                  \
            uint32_t _x = sbu + (S) * STG + XHOF + sXo;                       \
            _Pragma("unroll") for (int u = 0; u < KPT / 8; u++) {             \
                cpa16(_x + u * 16, pXH + _k + u * 8);                         \
                cpa16(_x + (XLOF - XHOF) + u * 16, pXL + _k + u * 8);         \
            }                                                                 \
        }                                                                     \
        asm volatile("cp.async.commit_group;" ::: "memory");                  \
    } while (0)

#define FETCHX(CH) do { const int _k = (CH) * KC;                             \
        _Pragma("unroll") for (int u = 0; u < XF; u++)                        \
            f[u] = *(const float4*)(xfp + _k + u * 4);                        \
    } while (0)

#define STOREX(S) do { char* _b = smem + (S) * STG;                           \
        _Pragma("unroll") for (int u = 0; u < XF / 2; u++) {                  \
            uint4 _H, _L; split8(f[2 * u], f[2 * u + 1], _H, _L);             \
            *(uint4*)(_b + XHOF + sXo + u * 16) = _H;                         \
            *(uint4*)(_b + XLOF + sXo + u * 16) = _L;                         \
        }                                                                     \
    } while (0)

#define COMPUTE(S) do { const uint32_t stb = sbu + (S) * STG;                 \
        _Pragma("unroll")                                                     \
        for (int ks = 0; ks < 2; ks++) {                                      \
            const int k0 = ks * 16;                                           \
            uint32_t bh[4][2], bl[4][2];                                      \
            _Pragma("unroll")                                                 \
            for (int p = 0; p < 2; p++) {                                     \
                const uint32_t nrow = wn * 32 + p * 16 + (l & 7) + ((l >> 4) << 3); \
                const uint32_t koff = k0 + (((l >> 3) & 1) << 3);             \
                const uint32_t ax = stb + XHOF + (nrow * STRB + koff) * 2;    \
                uint32_t r[4];                                                \
                ldm4(r, ax);                                                  \
                bh[2*p][0] = r[0]; bh[2*p][1] = r[1];                         \
                bh[2*p+1][0] = r[2]; bh[2*p+1][1] = r[3];                     \
                ldm4(r, ax + (XLOF - XHOF));                                  \
                bl[2*p][0] = r[0]; bl[2*p][1] = r[1];                         \
                bl[2*p+1][0] = r[2]; bl[2*p+1][1] = r[3];                     \
            }                                                                 \
            _Pragma("unroll")                                                 \
            for (int mt = 0; mt < MT; mt++) {                                 \
                const uint32_t mrow = wm * (MT * 16) + mt * 16 + (l & 15);    \
                const uint32_t koffA = k0 + ((l >> 4) << 3);                  \
                const uint32_t aa = stb + AHOF + (mrow * STRB + koffA) * 2;   \
                uint32_t ah[4], al[4];                                        \
                ldm4(ah, aa); ldm4(al, aa + (ALOF - AHOF));                   \
                _Pragma("unroll")                                             \
                for (int nt = 0; nt < 4; nt++) {                              \
                    mma16816(acc[mt][nt], ah, bh[nt]);                        \
                    mma16816(acc[mt][nt], ah, bl[nt]);                        \
                    mma16816(acc[mt][nt], al, bh[nt]);                        \
                }                                                             \
            }                                                                 \
        }                                                                     \
    } while (0)

    ASYNC_AB(0, 0);
    if (mode != M_POW) FETCHX(0);
    asm volatile("cp.async.wait_group 0;" ::: "memory");
    if (mode != M_POW) STOREX(0);
    __syncthreads();

    for (int ch = 0; ch < NCHK; ch++) {
        const bool more = (ch + 1 < NCHK);
        if (more) {
            ASYNC_AB(ch + 1, (ch + 1) & 1);
            if (mode != M_POW) FETCHX(ch + 1);
        }
        COMPUTE(ch & 1);
        if (more) {
            asm volatile("cp.async.wait_group 0;" ::: "memory");
            if (mode != M_POW) STOREX((ch + 1) & 1);
            __syncthreads();
        }
    }

    // ---------------- epilogue ----------------
#pragma unroll
    for (int mt = 0; mt < MT; mt++)
#pragma unroll
    for (int nt = 0; nt < 4; nt++) {
        float* cc = acc[mt][nt];
        const int cpa = c0 + wn * 32 + nt * 8 + (l & 3) * 2;
        const int elo = e0 + wm * (MT * 16) + mt * 16 + (l >> 2);
        if (cpa >= ncols) continue;
        if (mode == M_BX) {
            Of[(size_t)cpa * D + elo] = cc[0];
            Of[(size_t)(cpa + 1) * D + elo] = cc[1];
            Of[(size_t)cpa * D + elo + 8] = cc[2];
            Of[(size_t)(cpa + 1) * D + elo + 8] = cc[3];
        } else if (mode == M_POW) {
            const int zds = i4sel(zd, z);
#pragma unroll
            for (int q = 0; q < 4; q++) {
                const int e = elo + ((q >> 1) << 3);
                const int c = cpa + (q & 1);
                const float v = cc[q];
                __nv_bfloat16 h = __float2bfloat16(v);
                __nv_bfloat16 lo = __float2bfloat16(v - __bfloat162float(h));
                const size_t rm = (size_t)zds * DDm + (size_t)e * D + c;
                const size_t tm = (size_t)zds * DDm + (size_t)c * D + e;
                g_PH[rm] = h; g_PL[rm] = lo;
                g_PTH[tm] = h; g_PTL[tm] = lo;
                if (zds == 14) g_Pf[(size_t)e * D + c] = v;   // fp32 A^64
            }
        } else if (mode == M_SCAN) {
            const int b = cpa >> shN, j = cpa & mask;
            float* p0 = Of + ((size_t)b * Tl + (size_t)j * Cl + i) * D;
            float* p1 = p0 + (size_t)Cl * D;
            const float s0 = p0[elo] + cc[0];      p0[elo] = s0;
            const float s1 = p1[elo] + cc[1];      p1[elo] = s1;
            const float s2 = p0[elo + 8] + cc[2];  p0[elo + 8] = s2;
            const float s3 = p1[elo + 8] + cc[3];  p1[elo + 8] = s3;
            if (i == Cl - 1) {
                float* fw = Pf + ((size_t)b * (mask + 1) + j + 1) * D;
                fw[elo] = s0; fw[elo + 8] = s2;    // j even -> j < mask
                if (j + 1 < mask) {
                    float* f2 = Pf + ((size_t)b * (mask + 1) + j + 2) * D;
                    f2[elo] = s1; f2[elo + 8] = s3;
                }
            }
        } else {  // M_FIXZ
            const int b = cpa >> shN, j = cpa & mask;
            float* p0 = Of + ((size_t)b * Tl + (size_t)j * Cl + z) * D;
            float* p1 = p0 + (size_t)Cl * D;
            p0[elo] += cc[0]; p1[elo] += cc[1];
            p0[elo + 8] += cc[2]; p1[elo + 8] += cc[3];
        }
    }
#undef ASYNC_AB
#undef FETCHX
#undef STOREX
#undef COMPUTE
}

// ---------------- prep: split A (slot 0) and B (slot 15) ----------------
__global__ void prep_split(const float* __restrict__ A, const float* __restrict__ Bm) {
    const int idx = blockIdx.x * blockDim.x + threadIdx.x;  // 2*DDm
    const int off = idx & (DDm - 1);
    const int slot = (idx < DDm) ? 0 : 15;
    const float v = ((idx < DDm) ? A : Bm)[off];
    const int e = off >> 9, d = off & 511;
    __nv_bfloat16 h = __float2bfloat16(v);
    __nv_bfloat16 lo = __float2bfloat16(v - __bfloat162float(h));
    const size_t rm = (size_t)slot * DDm + off;
    const size_t tm = (size_t)slot * DDm + (size_t)d * D + e;
    g_PH[rm] = h; g_PL[rm] = lo;
    g_PTH[tm] = h; g_PTL[tm] = lo;
}

__global__ void seed_levels(const float* __restrict__ h0) {
    const int b = blockIdx.x, t = threadIdx.x;
    g_CB[(size_t)b * 512 * D + t] = h0[(size_t)b * D + t];
    g_DB[(size_t)b * 64 * D + t] = 0.f;
}

// ---- per-batch sequential scan of the 64 level-3 states with fp32 A^64 ----
__global__ void __launch_bounds__(512) l34_scan() {
    __shared__ float s[D];
    const int b = blockIdx.x, t = threadIdx.x;
    s[t] = 0.f;                       // DB[b,0] = 0 (seeded)
    __syncthreads();
    const float* row = g_Pf + (size_t)t * D;
    for (int m = 1; m < 64; m++) {
        float acc = 0.f;
#pragma unroll 8
        for (int k = 0; k < D; k += 4) {
            float4 a = *(const float4*)(row + k);
            acc += a.x * s[k] + a.y * s[k + 1] + a.z * s[k + 2] + a.w * s[k + 3];
        }
        acc += g_DB[((size_t)b * 64 + m) * D + t];
        __syncthreads();
        s[t] = acc;
        g_DB[((size_t)b * 64 + m) * D + t] = acc;
        __syncthreads();
    }
}

// ---------------- launcher ----------------
extern "C" void kernel_launch(void* const* d_in, const int* in_sizes, int n_in,
                              void* d_out, int out_size) {
    (void)in_sizes; (void)n_in; (void)out_size;
    const float* x  = (const float*)d_in[0];
    const float* h0 = (const float*)d_in[1];
    const float* A  = (const float*)d_in[2];
    const float* Bm = (const float*)d_in[3];
    float* out = (float*)d_out;

    static float *pCB = nullptr, *pDB;
    if (!pCB) {
        cudaGetSymbolAddress((void**)&pCB, g_CB);
        cudaGetSymbolAddress((void**)&pDB, g_DB);
        cudaFuncSetAttribute(tstep<64>, cudaFuncAttributeMaxDynamicSharedMemorySize,
                             2 * (20480 + 2 * 64 * 80));
    }
    const int SM64 = 2 * (20480 + 2 * 64 * 80);   // 61440 B
    const int4 zz = make_int4(0, 0, 0, 0);
#define TS(GX, GZ, ...) tstep<64><<<dim3(GX, 4, GZ), 256, SM64>>>(__VA_ARGS__)

    prep_split<<<2 * DDm / 256, 256>>>(A, Bm);

    // Bx: out[:,m] = B * x[m,:]   (32768 cols)
    TS(512, 1, x, out, nullptr, M_BX, 0, 0, 0, 0, 15, 32768, zz, zz, zz);

    // L1 local scan (A = slot 0), fold chunk ends -> CB[b, j+1]
    for (int i = 1; i < 8; i++)
        TS(64, 1, nullptr, out, pCB, M_SCAN, i, Tt, 8, 9, 0, 4096, zz, zz, zz);

    seed_levels<<<BSZ, D>>>(h0);

    // power tables: A^2..A^8 (slots 1..7), A^16..A^64 (slots 8..14)
#define PW(ZC, AZ, XZ, DZ) \
    TS(8, ZC, nullptr, nullptr, nullptr, M_POW, 0, 0, 0, 0, 0, 512, AZ, XZ, DZ)
    PW(1, make_int4(0,0,0,0),     make_int4(0,0,0,0),   make_int4(1,0,0,0));      // A^2
    PW(2, make_int4(1,1,0,0),     make_int4(0,1,0,0),   make_int4(2,3,0,0));      // A^3,A^4
    PW(4, make_int4(3,3,3,3),     make_int4(0,1,2,3),   make_int4(4,5,6,7));      // A^5..A^8
    PW(1, make_int4(7,0,0,0),     make_int4(7,0,0,0),   make_int4(8,0,0,0));      // A^16
    PW(2, make_int4(8,8,0,0),     make_int4(7,8,0,0),   make_int4(9,10,0,0));     // A^24,A^32
    PW(4, make_int4(10,10,10,10), make_int4(7,8,9,10),  make_int4(11,12,13,14));  // A^40..A^64
#undef PW

    // L2 local scan on CB (A^8 = slot 7), fold -> DB
    for (int i = 1; i < 8; i++)
        TS(8, 1, nullptr, pCB, pDB, M_SCAN, i, 512, 8, 6, 7, 512, zz, zz, zz);

    // L3+L4: per-batch sequential scan of DB with fp32 A^64
    l34_scan<<<BSZ, D>>>();

    // L2 fixup: CB[:,8m+z] += A^{8(z+1)} * DB[:,m]
    TS(8, 8, pDB, pCB, nullptr, M_FIXZ, 0, 512, 8, 6, 7, 512, zz, zz, zz);
    // L1 fixup: out[:,8j+z] += A^{z+1} * CB[:,j]
    TS(64, 8, pCB, out, nullptr, M_FIXZ, 0, Tt, 8, 9, 0, 4096, zz, zz, zz);
#undef TS
}

// round 16
// speedup vs baseline: 2.1251x; 2.0952x over previous
#include <cuda_runtime.h>
#include <cuda_bf16.h>
#include <cstdint>
#include <cstddef>

#define D     512
#define DDm   (D * D)
#define Tt    4096
#define BSZ   8
#define NSLOT 23      // 0..7: A^1..A^8 ; 7..14: A^8..A^64 ; 14..21: A^64..A^512 ; 22: B
#define KC    32
#define NCHK  16
#define STRB  40      // smem row stride in bf16 (80 B) -> conflict-free ldmatrix

__device__ __nv_bfloat16 g_PH[NSLOT * DDm];   // powers hi, row-major (A operand)
__device__ __nv_bfloat16 g_PL[NSLOT * DDm];   // lo
__device__ __nv_bfloat16 g_PTH[NSLOT * DDm];  // transposed hi (B operand for POW)
__device__ __nv_bfloat16 g_PTL[NSLOT * DDm];
__device__ float g_Pf[DDm];                   // fp32 A^512 (for l4 scan)
__device__ float g_CB[(BSZ * 512) * D];
__device__ float g_DB[(BSZ * 64) * D];
__device__ float g_EB[(BSZ * 8) * D];

enum { M_BX = 0, M_POW = 1, M_SCAN = 2, M_FIXZ = 3 };

__device__ __forceinline__ int i4sel(int4 v, int z) {
    return (z == 0) ? v.x : (z == 1) ? v.y : (z == 2) ? v.z : v.w;
}
__device__ __forceinline__ uint32_t s2u(const void* p) {
    uint32_t a;
    asm("{ .reg .u64 t; cvta.to.shared.u64 t, %1; cvt.u32.u64 %0, t; }" : "=r"(a) : "l"(p));
    return a;
}
__device__ __forceinline__ void split8(float4 a, float4 b, uint4& H, uint4& L) {
    __nv_bfloat162 h0 = __float22bfloat162_rn(make_float2(a.x, a.y));
    __nv_bfloat162 h1 = __float22bfloat162_rn(make_float2(a.z, a.w));
    __nv_bfloat162 h2 = __float22bfloat162_rn(make_float2(b.x, b.y));
    __nv_bfloat162 h3 = __float22bfloat162_rn(make_float2(b.z, b.w));
    float2 f0 = __bfloat1622float2(h0), f1 = __bfloat1622float2(h1);
    float2 f2 = __bfloat1622float2(h2), f3 = __bfloat1622float2(h3);
    __nv_bfloat162 l0 = __float22bfloat162_rn(make_float2(a.x - f0.x, a.y - f0.y));
    __nv_bfloat162 l1 = __float22bfloat162_rn(make_float2(a.z - f1.x, a.w - f1.y));
    __nv_bfloat162 l2 = __float22bfloat162_rn(make_float2(b.x - f2.x, b.y - f2.y));
    __nv_bfloat162 l3 = __float22bfloat162_rn(make_float2(b.z - f3.x, b.w - f3.y));
    H.x = *(uint32_t*)&h0; H.y = *(uint32_t*)&h1; H.z = *(uint32_t*)&h2; H.w = *(uint32_t*)&h3;
    L.x = *(uint32_t*)&l0; L.y = *(uint32_t*)&l1; L.z = *(uint32_t*)&l2; L.w = *(uint32_t*)&l3;
}
__device__ __forceinline__ void ldm4(uint32_t* r, uint32_t addr) {
    asm volatile("ldmatrix.sync.aligned.m8n8.x4.shared.b16 {%0,%1,%2,%3}, [%4];"
                 : "=r"(r[0]), "=r"(r[1]), "=r"(r[2]), "=r"(r[3]) : "r"(addr));
}
__device__ __forceinline__ void mma16816(float* c, const uint32_t* a, const uint32_t* b) {
    asm volatile("mma.sync.aligned.m16n8k16.row.col.f32.bf16.bf16.f32 "
                 "{%0,%1,%2,%3}, {%4,%5,%6,%7}, {%8,%9}, {%0,%1,%2,%3};"
                 : "+f"(c[0]), "+f"(c[1]), "+f"(c[2]), "+f"(c[3])
                 : "r"(a[0]), "r"(a[1]), "r"(a[2]), "r"(a[3]), "r"(b[0]), "r"(b[1]));
}
__device__ __forceinline__ void cpa16(uint32_t d, const void* s) {
    asm volatile("cp.async.cg.shared.global [%0], [%1], 16;" :: "r"(d), "l"(s) : "memory");
}

// ---------------------------------------------------------------------------
// HMMA unified step: 128 e-rows (blockIdx.y) x 64 cols (blockIdx.x), K = 512.
// 8 warps (4m x 2n), warp tile 32x32 (MT=2).  cp.async for bf16 A (and X in
// POW mode); register-split path for fp32 X operands.
// ---------------------------------------------------------------------------
template <int CPB>
__global__ void __launch_bounds__(256, 2) tstep(
    const float* __restrict__ Xf, float* __restrict__ Of, float* __restrict__ Pf,
    int mode, int i, int Tl, int Cl, int shN, int aslot, int ncols,
    int4 za, int4 zx, int4 zd)
{
    constexpr int WN = CPB / 32;          // warps along N (2)
    constexpr int MT = (128 * WN) / 128;  // m-tiles/warp (2)
    constexpr int AHOF = 0, ALOF = 10240, XHOF = 20480;
    constexpr int XLOF = 20480 + CPB * 80;
    constexpr int STG  = 20480 + 2 * CPB * 80;
    constexpr int TPC = 256 / CPB;        // threads per X col (4)
    constexpr int KPT = KC / TPC;         // k per X thread (8)
    constexpr int XF  = KPT / 4;          // float4 staged per X thread (2)
    static_assert(KPT >= 8 && XF >= 2, "X loader coverage");

    extern __shared__ char smem[];
    const uint32_t sbu = s2u(smem);
    const int tid = threadIdx.x, wid = tid >> 5, l = tid & 31;
    const int e0 = blockIdx.y * 128, c0 = blockIdx.x * CPB, z = blockIdx.z;
    const int mask = (1 << shN) - 1;
    const int wm = wid / WN, wn = wid % WN;

    const int as = (mode == M_POW) ? i4sel(za, z) : (mode == M_FIXZ) ? (aslot + z) : aslot;

    // ---- A loader (bf16 tables, cp.async): 128 rows x 32 k ----
    const int aRow = tid >> 1, aKq = (tid & 1) * 16;
    const __nv_bfloat16* pAH = g_PH + (size_t)as * DDm + (size_t)(e0 + aRow) * D + aKq;
    const __nv_bfloat16* pAL = g_PL + (size_t)as * DDm + (size_t)(e0 + aRow) * D + aKq;
    const uint32_t sAo = (uint32_t)(aRow * STRB + aKq) * 2;

    // ---- X loader: CPB cols x KC k over 256 threads ----
    const int xc = tid / TPC, xkq = (tid % TPC) * KPT;
    const uint32_t sXo = (uint32_t)(xc * STRB + xkq) * 2;
    const float* xfp = nullptr;
    const __nv_bfloat16 *pXH = nullptr, *pXL = nullptr;
    if (mode == M_POW) {
        const int xs = i4sel(zx, z);
        pXH = g_PTH + (size_t)xs * DDm + (size_t)(c0 + xc) * D + xkq;
        pXL = g_PTL + (size_t)xs * DDm + (size_t)(c0 + xc) * D + xkq;
    } else {
        const int c = c0 + xc;
        if (mode == M_SCAN) {
            const int b = c >> shN, j = c & mask;
            xfp = Of + ((size_t)b * Tl + (size_t)j * Cl + (i - 1)) * D + xkq;
        } else {
            xfp = Xf + (size_t)c * D + xkq;
        }
    }

    float acc[MT][4][4];
#pragma unroll
    for (int a = 0; a < MT; a++)
#pragma unroll
        for (int b = 0; b < 4; b++)
#pragma unroll
            for (int q = 0; q < 4; q++) acc[a][b][q] = 0.f;

    float4 f[XF];

#define ASYNC_AB(CH, S) do { const int _k = (CH) * KC;                        \
        uint32_t _d = sbu + (S) * STG + AHOF + sAo;                           \
        cpa16(_d, pAH + _k); cpa16(_d + 16, pAH + _k + 8);                    \
        cpa16(_d + (ALOF - AHOF), pAL + _k);                                  \
        cpa16(_d + (ALOF - AHOF) + 16, pAL + _k + 8);                         \
        if (mode == M_POW) {                                                  \
            uint32_t _x = sbu + (S) * STG + XHOF + sXo;                       \
            _Pragma("unroll") for (int u = 0; u < KPT / 8; u++) {             \
                cpa16(_x + u * 16, pXH + _k + u * 8);                         \
                cpa16(_x + (XLOF - XHOF) + u * 16, pXL + _k + u * 8);         \
            }                                                                 \
        }                                                                     \
        asm volatile("cp.async.commit_group;" ::: "memory");                  \
    } while (0)

#define FETCHX(CH) do { const int _k = (CH) * KC;                             \
        _Pragma("unroll") for (int u = 0; u < XF; u++)                        \
            f[u] = *(const float4*)(xfp + _k + u * 4);                        \
    } while (0)

#define STOREX(S) do { char* _b = smem + (S) * STG;                           \
        _Pragma("unroll") for (int u = 0; u < XF / 2; u++) {                  \
            uint4 _H, _L; split8(f[2 * u], f[2 * u + 1], _H, _L);             \
            *(uint4*)(_b + XHOF + sXo + u * 16) = _H;                         \
            *(uint4*)(_b + XLOF + sXo + u * 16) = _L;                         \
        }                                                                     \
    } while (0)

#define COMPUTE(S) do { const uint32_t stb = sbu + (S) * STG;                 \
        _Pragma("unroll")                                                     \
        for (int ks = 0; ks < 2; ks++) {                                      \
            const int k0 = ks * 16;                                           \
            uint32_t bh[4][2], bl[4][2];                                      \
            _Pragma("unroll")                                                 \
            for (int p = 0; p < 2; p++) {                                     \
                const uint32_t nrow = wn * 32 + p * 16 + (l & 7) + ((l >> 4) << 3); \
                const uint32_t koff = k0 + (((l >> 3) & 1) << 3);             \
                const uint32_t ax = stb + XHOF + (nrow * STRB + koff) * 2;    \
                uint32_t r[4];                                                \
                ldm4(r, ax);                                                  \
                bh[2*p][0] = r[0]; bh[2*p][1] = r[1];                         \
                bh[2*p+1][0] = r[2]; bh[2*p+1][1] = r[3];                     \
                ldm4(r, ax + (XLOF - XHOF));                                  \
                bl[2*p][0] = r[0]; bl[2*p][1] = r[1];                         \
                bl[2*p+1][0] = r[2]; bl[2*p+1][1] = r[3];                     \
            }                                                                 \
            _Pragma("unroll")                                                 \
            for (int mt = 0; mt < MT; mt++) {                                 \
                const uint32_t mrow = wm * (MT * 16) + mt * 16 + (l & 15);    \
                const uint32_t koffA = k0 + ((l >> 4) << 3);                  \
                const uint32_t aa = stb + AHOF + (mrow * STRB + koffA) * 2;   \
                uint32_t ah[4], al[4];                                        \
                ldm4(ah, aa); ldm4(al, aa + (ALOF - AHOF));                   \
                _Pragma("unroll")                                             \
                for (int nt = 0; nt < 4; nt++) {                              \
                    mma16816(acc[mt][nt], ah, bh[nt]);                        \
                    mma16816(acc[mt][nt], ah, bl[nt]);                        \
                    mma16816(acc[mt][nt], al, bh[nt]);                        \
                }                                                             \
            }                                                                 \
        }                                                                     \
    } while (0)

    ASYNC_AB(0, 0);
    if (mode != M_POW) FETCHX(0);
    asm volatile("cp.async.wait_group 0;" ::: "memory");
    if (mode != M_POW) STOREX(0);
    __syncthreads();

    for (int ch = 0; ch < NCHK; ch++) {
        const bool more = (ch + 1 < NCHK);
        if (more) {
            ASYNC_AB(ch + 1, (ch + 1) & 1);
            if (mode != M_POW) FETCHX(ch + 1);
        }
        COMPUTE(ch & 1);
        if (more) {
            asm volatile("cp.async.wait_group 0;" ::: "memory");
            if (mode != M_POW) STOREX((ch + 1) & 1);
            __syncthreads();
        }
    }

    // ---------------- epilogue ----------------
#pragma unroll
    for (int mt = 0; mt < MT; mt++)
#pragma unroll
    for (int nt = 0; nt < 4; nt++) {
        float* cc = acc[mt][nt];
        const int cpa = c0 + wn * 32 + nt * 8 + (l & 3) * 2;
        const int elo = e0 + wm * (MT * 16) + mt * 16 + (l >> 2);
        if (cpa >= ncols) continue;
        if (mode == M_BX) {
            Of[(size_t)cpa * D + elo] = cc[0];
            Of[(size_t)(cpa + 1) * D + elo] = cc[1];
            Of[(size_t)cpa * D + elo + 8] = cc[2];
            Of[(size_t)(cpa + 1) * D + elo + 8] = cc[3];
        } else if (mode == M_POW) {
            const int zds = i4sel(zd, z);
#pragma unroll
            for (int q = 0; q < 4; q++) {
                const int e = elo + ((q >> 1) << 3);
                const int c = cpa + (q & 1);
                const float v = cc[q];
                __nv_bfloat16 h = __float2bfloat16(v);
                __nv_bfloat16 lo = __float2bfloat16(v - __bfloat162float(h));
                const size_t rm = (size_t)zds * DDm + (size_t)e * D + c;
                const size_t tm = (size_t)zds * DDm + (size_t)c * D + e;
                g_PH[rm] = h; g_PL[rm] = lo;
                g_PTH[tm] = h; g_PTL[tm] = lo;
                if (zds == 21) g_Pf[(size_t)e * D + c] = v;   // fp32 A^512
            }
        } else if (mode == M_SCAN) {
            const int b = cpa >> shN, j = cpa & mask;
            float* p0 = Of + ((size_t)b * Tl + (size_t)j * Cl + i) * D;
            float* p1 = p0 + (size_t)Cl * D;
            const float s0 = p0[elo] + cc[0];      p0[elo] = s0;
            const float s1 = p1[elo] + cc[1];      p1[elo] = s1;
            const float s2 = p0[elo + 8] + cc[2];  p0[elo + 8] = s2;
            const float s3 = p1[elo + 8] + cc[3];  p1[elo + 8] = s3;
            if (i == Cl - 1) {
                float* fw = Pf + ((size_t)b * (mask + 1) + j + 1) * D;
                fw[elo] = s0; fw[elo + 8] = s2;    // j even -> j < mask
                if (j + 1 < mask) {
                    float* f2 = Pf + ((size_t)b * (mask + 1) + j + 2) * D;
                    f2[elo] = s1; f2[elo + 8] = s3;
                }
            }
        } else {  // M_FIXZ
            const int b = cpa >> shN, j = cpa & mask;
            float* p0 = Of + ((size_t)b * Tl + (size_t)j * Cl + z) * D;
            float* p1 = p0 + (size_t)Cl * D;
            p0[elo] += cc[0]; p1[elo] += cc[1];
            p0[elo + 8] += cc[2]; p1[elo + 8] += cc[3];
        }
    }
#undef ASYNC_AB
#undef FETCHX
#undef STOREX
#undef COMPUTE
}

// ---------------- prep: split A (slot 0) and B (slot 22) ----------------
__global__ void prep_split(const float* __restrict__ A, const float* __restrict__ Bm) {
    const int idx = blockIdx.x * blockDim.x + threadIdx.x;  // 2*DDm
    const int off = idx & (DDm - 1);
    const int slot = (idx < DDm) ? 0 : 22;
    const float v = ((idx < DDm) ? A : Bm)[off];
    const int e = off >> 9, d = off & 511;
    __nv_bfloat16 h = __float2bfloat16(v);
    __nv_bfloat16 lo = __float2bfloat16(v - __bfloat162float(h));
    const size_t rm = (size_t)slot * DDm + off;
    const size_t tm = (size_t)slot * DDm + (size_t)d * D + e;
    g_PH[rm] = h; g_PL[rm] = lo;
    g_PTH[tm] = h; g_PTL[tm] = lo;
}

__global__ void seed_levels(const float* __restrict__ h0) {
    const int b = blockIdx.x, t = threadIdx.x;
    g_CB[(size_t)b * 512 * D + t] = h0[(size_t)b * D + t];
    g_DB[(size_t)b * 64 * D + t] = 0.f;
    g_EB[(size_t)b * 8 * D + t] = 0.f;
}

// ---- level-4: per-batch sequential scan of 8 states with fp32 A^512 ----
__global__ void __launch_bounds__(512) l4_scan() {
    __shared__ float s[D];
    const int b = blockIdx.x, t = threadIdx.x;
    s[t] = 0.f;                       // e_0 = 0 (EB[b,0] stays 0)
    __syncthreads();
    const float* row = g_Pf + (size_t)t * D;
    for (int p = 1; p < 8; p++) {
        float acc = 0.f;
#pragma unroll 8
        for (int k = 0; k < D; k += 4) {
            float4 a = *(const float4*)(row + k);
            acc += a.x * s[k] + a.y * s[k + 1] + a.z * s[k + 2] + a.w * s[k + 3];
        }
        acc += g_EB[((size_t)b * 8 + p) * D + t];
        __syncthreads();
        s[t] = acc;
        g_EB[((size_t)b * 8 + p) * D + t] = acc;
        __syncthreads();
    }
}

// ---------------- launcher ----------------
extern "C" void kernel_launch(void* const* d_in, const int* in_sizes, int n_in,
                              void* d_out, int out_size) {
    (void)in_sizes; (void)n_in; (void)out_size;
    const float* x  = (const float*)d_in[0];
    const float* h0 = (const float*)d_in[1];
    const float* A  = (const float*)d_in[2];
    const float* Bm = (const float*)d_in[3];
    float* out = (float*)d_out;

    static float *pCB = nullptr, *pDB, *pEB;
    if (!pCB) {
        cudaGetSymbolAddress((void**)&pCB, g_CB);
        cudaGetSymbolAddress((void**)&pDB, g_DB);
        cudaGetSymbolAddress((void**)&pEB, g_EB);
        cudaFuncSetAttribute(tstep<64>, cudaFuncAttributeMaxDynamicSharedMemorySize,
                             2 * (20480 + 2 * 64 * 80));
    }
    const int SM64 = 2 * (20480 + 2 * 64 * 80);   // 61440 B
    const int4 zz = make_int4(0, 0, 0, 0);
#define TS(GX, GZ, ...) tstep<64><<<dim3(GX, 4, GZ), 256, SM64>>>(__VA_ARGS__)

    prep_split<<<2 * DDm / 256, 256>>>(A, Bm);

    // Bx: out[:,m] = B * x[m,:]   (32768 cols)
    TS(512, 1, x, out, nullptr, M_BX, 0, 0, 0, 0, 22, 32768, zz, zz, zz);

    // L1 local scan (A = slot 0), fold chunk ends -> CB[b, j+1]
    for (int i = 1; i < 8; i++)
        TS(64, 1, nullptr, out, pCB, M_SCAN, i, Tt, 8, 9, 0, 4096, zz, zz, zz);

    seed_levels<<<BSZ, D>>>(h0);

    // power tables: A^2..A^8 (1..7), A^16..A^64 (8..14), A^128..A^512 (15..21)
#define PW(ZC, AZ, XZ, DZ) \
    TS(8, ZC, nullptr, nullptr, nullptr, M_POW, 0, 0, 0, 0, 0, 512, AZ, XZ, DZ)
    PW(1, make_int4(0,0,0,0),     make_int4(0,0,0,0),     make_int4(1,0,0,0));      // A^2
    PW(2, make_int4(1,1,0,0),     make_int4(0,1,0,0),     make_int4(2,3,0,0));      // A^3,A^4
    PW(4, make_int4(3,3,3,3),     make_int4(0,1,2,3),     make_int4(4,5,6,7));      // A^5..A^8
    PW(1, make_int4(7,0,0,0),     make_int4(7,0,0,0),     make_int4(8,0,0,0));      // A^16
    PW(2, make_int4(8,8,0,0),     make_int4(7,8,0,0),     make_int4(9,10,0,0));     // A^24,A^32
    PW(4, make_int4(10,10,10,10), make_int4(7,8,9,10),    make_int4(11,12,13,14));  // A^40..A^64
    PW(1, make_int4(14,0,0,0),    make_int4(14,0,0,0),    make_int4(15,0,0,0));     // A^128
    PW(2, make_int4(15,15,0,0),   make_int4(14,15,0,0),   make_int4(16,17,0,0));    // A^192,A^256
    PW(4, make_int4(17,17,17,17), make_int4(14,15,16,17), make_int4(18,19,20,21));  // A^320..A^512
#undef PW

    // L2 local scan on CB (A^8 = slot 7), fold -> DB
    for (int i = 1; i < 8; i++)
        TS(8, 1, nullptr, pCB, pDB, M_SCAN, i, 512, 8, 6, 7, 512, zz, zz, zz);

    // L3 local scan on DB (A^64 = slot 14), fold -> EB
    for (int i = 1; i < 8; i++)
        TS(1, 1, nullptr, pDB, pEB, M_SCAN, i, 64, 8, 3, 14, 64, zz, zz, zz);

    // L4 boundary scan (A^512 fp32, 7 sequential matvecs)
    l4_scan<<<BSZ, D>>>();

    // L3 fixup: DB[:,8p+z] += A^{64(z+1)} * EB[:,p]
    TS(1, 8, pEB, pDB, nullptr, M_FIXZ, 0, 64, 8, 3, 14, 64, zz, zz, zz);
    // L2 fixup: CB[:,8m+z] += A^{8(z+1)} * DB[:,m]
    TS(8, 8, pDB, pCB, nullptr, M_FIXZ, 0, 512, 8, 6, 7, 512, zz, zz, zz);
    // L1 fixup: out[:,8j+z] += A^{z+1} * CB[:,j]
    TS(64, 8, pCB, out, nullptr, M_FIXZ, 0, Tt, 8, 9, 0, 4096, zz, zz, zz);
#undef TS
}